// round 13
// baseline (speedup 1.0000x reference)
#include <cuda_runtime.h>
#include <cuda_fp16.h>
#include <cstdint>

constexpr int Hh = 8, DH = 64, INNER = 512, QLEN = 4096, KLEN = 308, CL = 77, CP = 80;
constexpr int QT = 64, NQT = QLEN / QT;     // 64 query tiles of 64 rows
constexpr int TPB = 128;                    // 4 warps
constexpr int LDH = 72;                     // halves per smem row (144B, ldmatrix conflict-free)

// device scratch
__device__ __half g_kh[2 * KLEN * INNER];
__device__ __half g_vh[2 * KLEN * INNER];
__device__ float  g_cs[4];                  // (128/sum)*log2(e)
__device__ unsigned char g_act[QLEN];

// smem: Q (fp16, 64 rows) + single K buffer + single V buffer
constexpr int KV_BYTES = CP * LDH * 2;            // 11520
constexpr int OFF_QH = 0;
constexpr int OFF_K  = OFF_QH + QT * LDH * 2;     // 9216
constexpr int OFF_V  = OFF_K + KV_BYTES;          // 20736
constexpr int SMEM_BYTES = OFF_V + KV_BYTES;      // 32256 -> 7 CTAs/SM (220.5KB)

__device__ __forceinline__ uint32_t h2u(float a, float b) {
    __half2 h = __floats2half2_rn(a, b);
    return *reinterpret_cast<uint32_t*>(&h);
}
__device__ __forceinline__ float ex2(float x) {
    float r; asm("ex2.approx.f32 %0, %1;" : "=f"(r) : "f"(x)); return r;
}
__device__ __forceinline__ void ldsm_x4(uint32_t* r, uint32_t addr) {
    asm volatile("ldmatrix.sync.aligned.m8n8.x4.shared.b16 {%0,%1,%2,%3}, [%4];"
                 : "=r"(r[0]), "=r"(r[1]), "=r"(r[2]), "=r"(r[3]) : "r"(addr));
}
__device__ __forceinline__ void ldsm_x4_t(uint32_t* r, uint32_t addr) {
    asm volatile("ldmatrix.sync.aligned.m8n8.x4.trans.shared.b16 {%0,%1,%2,%3}, [%4];"
                 : "=r"(r[0]), "=r"(r[1]), "=r"(r[2]), "=r"(r[3]) : "r"(addr));
}
__device__ __forceinline__ void mma16816(float* c, const uint32_t* a, uint32_t b0, uint32_t b1) {
    asm volatile("mma.sync.aligned.m16n8k16.row.col.f32.f16.f16.f32 "
                 "{%0,%1,%2,%3},{%4,%5,%6,%7},{%8,%9},{%0,%1,%2,%3};"
                 : "+f"(c[0]), "+f"(c[1]), "+f"(c[2]), "+f"(c[3])
                 : "r"(a[0]), "r"(a[1]), "r"(a[2]), "r"(a[3]), "r"(b0), "r"(b1));
}
__device__ __forceinline__ void cpa16(uint32_t s, const void* g) {
    asm volatile("cp.async.cg.shared.global [%0], [%1], 16;" :: "r"(s), "l"(g));
}

// ---------------------------------------------------------------------------
// prep: K,V -> fp16; region scales (x log2e); per-query activity bytes
// ---------------------------------------------------------------------------
__global__ void __launch_bounds__(256) prep_kernel(const float* __restrict__ k,
                                                   const float* __restrict__ v,
                                                   const float* __restrict__ dd)
{
    int blk = blockIdx.x, tid = threadIdx.x;
    if (blk < 308) {
        int idx = (blk * 256 + tid) * 4;               // over 2*308*512 floats
        float4 kf = *reinterpret_cast<const float4*>(k + idx);
        float4 vf = *reinterpret_cast<const float4*>(v + idx);
        *reinterpret_cast<uint2*>(reinterpret_cast<char*>(g_kh) + (size_t)idx * 2) =
            make_uint2(h2u(kf.x, kf.y), h2u(kf.z, kf.w));
        *reinterpret_cast<uint2*>(reinterpret_cast<char*>(g_vh) + (size_t)idx * 2) =
            make_uint2(h2u(vf.x, vf.y), h2u(vf.z, vf.w));
    } else if (blk == 308) {
        __shared__ float ws[4][8];
        int w = tid >> 5, l = tid & 31;
        #pragma unroll
        for (int r = 0; r < 4; r++) {
            float s = 0.f;
            #pragma unroll
            for (int i = 0; i < 4; i++) s += dd[r * 1024 + i * 256 + tid];
            #pragma unroll
            for (int o = 16; o > 0; o >>= 1) s += __shfl_xor_sync(0xffffffffu, s, o, 32);
            if (l == 0) ws[r][w] = s;
        }
        __syncthreads();
        if (tid < 4) {
            float s = 0.f;
            #pragma unroll
            for (int ww = 0; ww < 8; ww++) s += ws[tid][ww];
            g_cs[tid] = (128.f / s) * 1.4426950408889634f;
        }
    } else {
        int qg = (blk - 309) * 256 + tid;              // 16 blocks -> 4096
        int y = qg >> 6, x = qg & 63;
        unsigned a = 0;
        #pragma unroll
        for (int r = 0; r < 4; r++)
            if (dd[r * 1024 + (y >> 1) * 32 + (x >> 1)] > 0.5f) a |= 1u << r;
        g_act[qg] = (unsigned char)a;
    }
}

// ---------------------------------------------------------------------------
// main: fp16 mma.sync attention; M=64 CTAs; 7 CTAs/SM; split K/V staging
// phases overlap cp.async latency with compute (no extra smem).
// ---------------------------------------------------------------------------
__global__ void __launch_bounds__(TPB, 7)
ddca_kernel(const float* __restrict__ q, float* __restrict__ out)
{
    extern __shared__ char smc[];
    half* Qh = (half*)(smc + OFF_QH);
    uint32_t sbase = (uint32_t)__cvta_generic_to_shared(smc);
    const uint32_t qh_b = sbase + OFF_QH;
    const uint32_t k_b  = sbase + OFF_K;
    const uint32_t v_b  = sbase + OFF_V;

    const int tid = threadIdx.x, w = tid >> 5, lane = tid & 31;
    const int gid = lane >> 2, tig = lane & 3;
    const int bid = blockIdx.x;
    const int qt = bid & 63, bh = bid >> 6, h = bh & 7, b = bh >> 3;

    const float* qp = q + ((size_t)b * QLEN + (size_t)qt * QT) * INNER + h * DH;
    const size_t kvbase = (size_t)b * KLEN * INNER + h * DH;

    // zero V pad rows 77..79 (never overwritten by staging)
    if (tid < 108)
        reinterpret_cast<uint32_t*>(smc + OFF_V + 77 * LDH * 2)[tid] = 0;

    // prologue: stage K0 (group), then V0 (group)
    for (int i = tid; i < CL * 8; i += TPB) {
        int kk = i >> 3, d8 = (i & 7) * 8;
        cpa16(k_b + (uint32_t)(kk * LDH + d8) * 2, g_kh + kvbase + (size_t)kk * INNER + d8);
    }
    asm volatile("cp.async.commit_group;");
    for (int i = tid; i < CL * 8; i += TPB) {
        int kk = i >> 3, d8 = (i & 7) * 8;
        cpa16(v_b + (uint32_t)(kk * LDH + d8) * 2, g_vh + kvbase + (size_t)kk * INNER + d8);
    }
    asm volatile("cp.async.commit_group;");

    // stage Q (fp16 rounded)
    #pragma unroll
    for (int it = 0; it < 8; it++) {
        int i4 = tid + it * TPB;
        int row = i4 >> 4, dq = (i4 & 15) * 4;
        float4 t = *reinterpret_cast<const float4*>(qp + (size_t)row * INNER + dq);
        *reinterpret_cast<uint2*>(Qh + row * LDH + dq) =
            make_uint2(h2u(t.x, t.y), h2u(t.z, t.w));
    }

    const unsigned a0 = g_act[qt * QT + 16 * w + gid];
    const unsigned a1 = g_act[qt * QT + 16 * w + gid + 8];
    float csr[4];
    #pragma unroll
    for (int r = 0; r < 4; r++) csr[r] = g_cs[r];

    const int qrow  = 16 * w + (lane & 15);
    const int qcol0 = (lane >> 4) << 3;
    const int krow  = (lane & 7) + ((lane >> 4) << 3);
    const int kcol0 = ((lane >> 3) & 1) << 3;

    float O[8][4];
    #pragma unroll
    for (int n = 0; n < 8; n++)
        #pragma unroll
        for (int e = 0; e < 4; e++) O[n][e] = 0.f;
    float L0 = 0.f, L1 = 0.f;

    const bool bk0 = (tig <= 2), bk1 = (tig < 2);   // chunk col 72+2tig(+1) < 77

    #pragma unroll 1
    for (int c = 0; c < 4; c++) {
        // A: K(c) ready (commit order ...K(c),V(c): allow V(c) outstanding)
        asm volatile("cp.async.wait_group 1;");
        __syncthreads();

        const float c2 = csr[c];
        const bool r0a = (a0 >> c) & 1, r1a = (a1 >> c) & 1;

        // Q fragments (reload per chunk; Q smem is stable)
        uint32_t qf[4][4];
        #pragma unroll
        for (int kt = 0; kt < 4; kt++)
            ldsm_x4(qf[kt], qh_b + (uint32_t)(qrow * LDH + 16 * kt + qcol0) * 2);

        // ---- QK phase: S tiles for all 5 np (kept small: stream into exp) ----
        float S[10][4];
        #pragma unroll
        for (int j = 0; j < 10; j++)
            #pragma unroll
            for (int e = 0; e < 4; e++) S[j][e] = 0.f;
        #pragma unroll
        for (int kt = 0; kt < 4; kt++) {
            #pragma unroll
            for (int np = 0; np < 5; np++) {
                uint32_t bhf[4];
                ldsm_x4(bhf, k_b + (uint32_t)((16 * np + krow) * LDH + 16 * kt + kcol0) * 2);
                mma16816(S[2 * np],     qf[kt], bhf[0], bhf[1]);
                mma16816(S[2 * np + 1], qf[kt], bhf[2], bhf[3]);
            }
        }

        // B: done reading K; stage K(c+1) (overlaps exp + PV below)
        __syncthreads();
        if (c < 3) {
            for (int i = tid; i < CL * 8; i += TPB) {
                int kk = i >> 3, d8 = (i & 7) * 8;
                cpa16(k_b + (uint32_t)(kk * LDH + d8) * 2,
                      g_kh + kvbase + (size_t)((c + 1) * CL + kk) * INNER + d8);
            }
            asm volatile("cp.async.commit_group;");
        }

        // ---- exp phase ----
        uint32_t pA[5][4];
        #pragma unroll
        for (int kt2 = 0; kt2 < 5; kt2++) {
            int j0 = 2 * kt2, j1 = 2 * kt2 + 1;
            bool o10 = (j1 < 9) || bk0, o11 = (j1 < 9) || bk1;
            float e00 = r0a          ? ex2(fmaf(S[j0][0], c2, -8.f)) : 0.f;
            float e01 = r0a          ? ex2(fmaf(S[j0][1], c2, -8.f)) : 0.f;
            float e02 = r1a          ? ex2(fmaf(S[j0][2], c2, -8.f)) : 0.f;
            float e03 = r1a          ? ex2(fmaf(S[j0][3], c2, -8.f)) : 0.f;
            float e10 = (r0a && o10) ? ex2(fmaf(S[j1][0], c2, -8.f)) : 0.f;
            float e11 = (r0a && o11) ? ex2(fmaf(S[j1][1], c2, -8.f)) : 0.f;
            float e12 = (r1a && o10) ? ex2(fmaf(S[j1][2], c2, -8.f)) : 0.f;
            float e13 = (r1a && o11) ? ex2(fmaf(S[j1][3], c2, -8.f)) : 0.f;
            L0 += (e00 + e01) + (e10 + e11);
            L1 += (e02 + e03) + (e12 + e13);
            pA[kt2][0] = h2u(e00, e01);
            pA[kt2][1] = h2u(e02, e03);
            pA[kt2][2] = h2u(e10, e11);
            pA[kt2][3] = h2u(e12, e13);
        }

        // C: V(c) ready (allow K(c+1) outstanding)
        if (c < 3) asm volatile("cp.async.wait_group 1;");
        else       asm volatile("cp.async.wait_group 0;");
        __syncthreads();

        // ---- PV phase ----
        #pragma unroll
        for (int kt2 = 0; kt2 < 5; kt2++) {
            #pragma unroll
            for (int dp = 0; dp < 4; dp++) {
                uint32_t vf[4];
                ldsm_x4_t(vf, v_b + (uint32_t)((16 * kt2 + krow) * LDH + 16 * dp + kcol0) * 2);
                mma16816(O[2 * dp],     pA[kt2], vf[0], vf[2]);
                mma16816(O[2 * dp + 1], pA[kt2], vf[1], vf[3]);
            }
        }

        // D: done reading V; stage V(c+1) (overlaps next chunk's QK + exp)
        __syncthreads();
        if (c < 3) {
            for (int i = tid; i < CL * 8; i += TPB) {
                int kk = i >> 3, d8 = (i & 7) * 8;
                cpa16(v_b + (uint32_t)(kk * LDH + d8) * 2,
                      g_vh + kvbase + (size_t)((c + 1) * CL + kk) * INNER + d8);
            }
            asm volatile("cp.async.commit_group;");
        }
    }

    // ---- final L reduction; write out ----
    L0 += __shfl_xor_sync(0xffffffffu, L0, 1);
    L0 += __shfl_xor_sync(0xffffffffu, L0, 2);
    L1 += __shfl_xor_sync(0xffffffffu, L1, 1);
    L1 += __shfl_xor_sync(0xffffffffu, L1, 2);
    const float i0 = 1.f / L0, i1 = 1.f / L1;
    float* o0 = out + ((size_t)b * QLEN + (size_t)qt * QT + 16 * w + gid) * INNER + h * DH + 2 * tig;
    float* o1 = o0 + (size_t)8 * INNER;
    #pragma unroll
    for (int n = 0; n < 8; n++) {
        *reinterpret_cast<float2*>(o0 + 8 * n) = make_float2(O[n][0] * i0, O[n][1] * i0);
        *reinterpret_cast<float2*>(o1 + 8 * n) = make_float2(O[n][2] * i1, O[n][3] * i1);
    }
}

extern "C" void kernel_launch(void* const* d_in, const int* in_sizes, int n_in,
                              void* d_out, int out_size) {
    const float* q  = (const float*)d_in[0];
    const float* k  = (const float*)d_in[1];
    const float* v  = (const float*)d_in[2];
    const float* dd = (const float*)d_in[3];
    float* out = (float*)d_out;

    prep_kernel<<<325, 256>>>(k, v, dd);

    cudaFuncSetAttribute(ddca_kernel,
                         cudaFuncAttributeMaxDynamicSharedMemorySize, SMEM_BYTES);
    ddca_kernel<<<2 * Hh * NQT, TPB, SMEM_BYTES>>>(q, out);   // 1024 CTAs
}

// round 14
// speedup vs baseline: 1.2089x; 1.2089x over previous
#include <cuda_runtime.h>
#include <cuda_fp16.h>
#include <cstdint>

constexpr int Hh = 8, DH = 64, INNER = 512, QLEN = 4096, KLEN = 308, CL = 77, CP = 80;
constexpr int QT = 64, NQT = QLEN / QT;     // 64 query tiles of 64 rows
constexpr int TPB = 128;                    // 4 warps
constexpr int LDH = 72;                     // halves per smem row (144B, ldmatrix conflict-free)

// device scratch
__device__ __half g_kh[2 * KLEN * INNER];
__device__ __half g_vh[2 * KLEN * INNER];
__device__ float  g_cs[4];                  // (128/sum)*log2(e)
__device__ unsigned char g_act[QLEN];

// smem: Q (fp16, 64 rows) + single K buffer + single V buffer
constexpr int KV_BYTES = CP * LDH * 2;            // 11520
constexpr int OFF_QH = 0;
constexpr int OFF_K  = OFF_QH + QT * LDH * 2;     // 9216
constexpr int OFF_V  = OFF_K + KV_BYTES;          // 20736
constexpr int SMEM_BYTES = OFF_V + KV_BYTES;      // 32256

__device__ __forceinline__ uint32_t h2u(float a, float b) {
    __half2 h = __floats2half2_rn(a, b);
    return *reinterpret_cast<uint32_t*>(&h);
}
// pack {lo=exp2(zlo), hi=exp2(zhi)} computed in fp16x2
__device__ __forceinline__ uint32_t cvtex2(float zlo, float zhi) {
    uint32_t t, d;
    asm("cvt.rn.satfinite.f16x2.f32 %0, %1, %2;" : "=r"(t) : "f"(zhi), "f"(zlo));
    asm("ex2.approx.f16x2 %0, %1;" : "=r"(d) : "r"(t));
    return d;
}
__device__ __forceinline__ void ldsm_x4(uint32_t* r, uint32_t addr) {
    asm volatile("ldmatrix.sync.aligned.m8n8.x4.shared.b16 {%0,%1,%2,%3}, [%4];"
                 : "=r"(r[0]), "=r"(r[1]), "=r"(r[2]), "=r"(r[3]) : "r"(addr));
}
__device__ __forceinline__ void ldsm_x4_t(uint32_t* r, uint32_t addr) {
    asm volatile("ldmatrix.sync.aligned.m8n8.x4.trans.shared.b16 {%0,%1,%2,%3}, [%4];"
                 : "=r"(r[0]), "=r"(r[1]), "=r"(r[2]), "=r"(r[3]) : "r"(addr));
}
__device__ __forceinline__ void ldsm_x2_t(uint32_t* r, uint32_t addr) {
    asm volatile("ldmatrix.sync.aligned.m8n8.x2.trans.shared.b16 {%0,%1}, [%2];"
                 : "=r"(r[0]), "=r"(r[1]) : "r"(addr));
}
__device__ __forceinline__ void mma16816(float* c, const uint32_t* a, uint32_t b0, uint32_t b1) {
    asm volatile("mma.sync.aligned.m16n8k16.row.col.f32.f16.f16.f32 "
                 "{%0,%1,%2,%3},{%4,%5,%6,%7},{%8,%9},{%0,%1,%2,%3};"
                 : "+f"(c[0]), "+f"(c[1]), "+f"(c[2]), "+f"(c[3])
                 : "r"(a[0]), "r"(a[1]), "r"(a[2]), "r"(a[3]), "r"(b0), "r"(b1));
}
__device__ __forceinline__ void cpa16(uint32_t s, const void* g) {
    asm volatile("cp.async.cg.shared.global [%0], [%1], 16;" :: "r"(s), "l"(g));
}

// ---------------------------------------------------------------------------
// prep: K,V -> fp16; region scales (x log2e); per-query activity bytes
// ---------------------------------------------------------------------------
__global__ void __launch_bounds__(256) prep_kernel(const float* __restrict__ k,
                                                   const float* __restrict__ v,
                                                   const float* __restrict__ dd)
{
    int blk = blockIdx.x, tid = threadIdx.x;
    if (blk < 308) {
        int idx = (blk * 256 + tid) * 4;               // over 2*308*512 floats
        float4 kf = *reinterpret_cast<const float4*>(k + idx);
        float4 vf = *reinterpret_cast<const float4*>(v + idx);
        *reinterpret_cast<uint2*>(reinterpret_cast<char*>(g_kh) + (size_t)idx * 2) =
            make_uint2(h2u(kf.x, kf.y), h2u(kf.z, kf.w));
        *reinterpret_cast<uint2*>(reinterpret_cast<char*>(g_vh) + (size_t)idx * 2) =
            make_uint2(h2u(vf.x, vf.y), h2u(vf.z, vf.w));
    } else if (blk == 308) {
        __shared__ float ws[4][8];
        int w = tid >> 5, l = tid & 31;
        #pragma unroll
        for (int r = 0; r < 4; r++) {
            float s = 0.f;
            #pragma unroll
            for (int i = 0; i < 4; i++) s += dd[r * 1024 + i * 256 + tid];
            #pragma unroll
            for (int o = 16; o > 0; o >>= 1) s += __shfl_xor_sync(0xffffffffu, s, o, 32);
            if (l == 0) ws[r][w] = s;
        }
        __syncthreads();
        if (tid < 4) {
            float s = 0.f;
            #pragma unroll
            for (int ww = 0; ww < 8; ww++) s += ws[tid][ww];
            g_cs[tid] = (128.f / s) * 1.4426950408889634f;
        }
    } else {
        int qg = (blk - 309) * 256 + tid;              // 16 blocks -> 4096
        int y = qg >> 6, x = qg & 63;
        unsigned a = 0;
        #pragma unroll
        for (int r = 0; r < 4; r++)
            if (dd[r * 1024 + (y >> 1) * 32 + (x >> 1)] > 0.5f) a |= 1u << r;
        g_act[qg] = (unsigned char)a;
    }
}

// ---------------------------------------------------------------------------
// main: fp16 mma.sync attention (R11 structure) + fp16x2 exp + L as V col 64
// ---------------------------------------------------------------------------
__global__ void __launch_bounds__(TPB, 6)
ddca_kernel(const float* __restrict__ q, float* __restrict__ out)
{
    extern __shared__ char smc[];
    half* Qh = (half*)(smc + OFF_QH);
    uint32_t sbase = (uint32_t)__cvta_generic_to_shared(smc);
    const uint32_t qh_b = sbase + OFF_QH;
    const uint32_t k_b  = sbase + OFF_K;
    const uint32_t v_b  = sbase + OFF_V;

    const int tid = threadIdx.x, w = tid >> 5, lane = tid & 31;
    const int gid = lane >> 2, tig = lane & 3;
    const int bid = blockIdx.x;
    const int qt = bid & 63, bh = bid >> 6, h = bh & 7, b = bh >> 3;

    const float* qp = q + ((size_t)b * QLEN + (size_t)qt * QT) * INNER + h * DH;
    const size_t kvbase = (size_t)b * KLEN * INNER + h * DH;

    // zero V pad rows 77..79 cols 0..71, and K pad rows 77..79 (NaN safety)
    if (tid < 108) {
        reinterpret_cast<uint32_t*>(smc + OFF_V + 77 * LDH * 2)[tid] = 0;
        reinterpret_cast<uint32_t*>(smc + OFF_K + 77 * LDH * 2)[tid] = 0;
    }
    // ones column: rows 0..79, col 64 = 1.0h, cols 65..71 = 0 (never restaged)
    if (tid < 80) {
        *reinterpret_cast<uint4*>(reinterpret_cast<half*>(smc + OFF_V) + tid * LDH + 64) =
            make_uint4(0x00003C00u, 0u, 0u, 0u);
    }

    // prologue: stage chunk 0 K/V (rows 0..76, cols 0..63)
    for (int i = tid; i < CL * 8; i += TPB) {
        int kk = i >> 3, d8 = (i & 7) * 8;
        size_t off = kvbase + (size_t)kk * INNER + d8;
        uint32_t so = (uint32_t)(kk * LDH + d8) * 2;
        cpa16(k_b + so, g_kh + off);
        cpa16(v_b + so, g_vh + off);
    }
    asm volatile("cp.async.commit_group;");

    // stage Q (fp16 rounded)
    #pragma unroll
    for (int it = 0; it < 8; it++) {
        int i4 = tid + it * TPB;
        int row = i4 >> 4, dq = (i4 & 15) * 4;
        float4 t = *reinterpret_cast<const float4*>(qp + (size_t)row * INNER + dq);
        *reinterpret_cast<uint2*>(Qh + row * LDH + dq) =
            make_uint2(h2u(t.x, t.y), h2u(t.z, t.w));
    }

    const unsigned a0 = g_act[qt * QT + 16 * w + gid];
    const unsigned a1 = g_act[qt * QT + 16 * w + gid + 8];
    float csr[4];
    #pragma unroll
    for (int r = 0; r < 4; r++) csr[r] = g_cs[r];

    const int qrow  = 16 * w + (lane & 15);
    const int qcol0 = (lane >> 4) << 3;
    const int krow  = (lane & 7) + ((lane >> 4) << 3);
    const int kcol0 = ((lane >> 3) & 1) << 3;

    float O[8][4];
    #pragma unroll
    for (int n = 0; n < 8; n++)
        #pragma unroll
        for (int e = 0; e < 4; e++) O[n][e] = 0.f;
    float LO[4] = {0.f, 0.f, 0.f, 0.f};          // L accumulator fragment (col 64)
    uint32_t qf[4][4];
    bool qload = false;

    const bool bk0 = (tig <= 2), bk1 = (tig < 2);   // chunk col 72+2tig(+1) < 77

    #pragma unroll 1
    for (int c = 0; c < 4; c++) {
        asm volatile("cp.async.wait_group 0;");
        __syncthreads();                      // K/V chunk c (and Q on c=0) visible

        if (!qload) {
            #pragma unroll
            for (int kt = 0; kt < 4; kt++)
                ldsm_x4(qf[kt], qh_b + (uint32_t)(qrow * LDH + 16 * kt + qcol0) * 2);
            qload = true;
        }

        const float c2 = csr[c];
        const float aR0 = ((a0 >> c) & 1) ? -8.f : -1e30f;
        const float aR1 = ((a1 >> c) & 1) ? -8.f : -1e30f;
        const float aB0e = bk0 ? aR0 : -1e30f, aB0o = bk1 ? aR0 : -1e30f;
        const float aB1e = bk0 ? aR1 : -1e30f, aB1o = bk1 ? aR1 : -1e30f;

        // ---- streamed per-16-key tile: S-tile -> exp(f16x2) -> O += P V ----
        #pragma unroll
        for (int np = 0; np < 5; np++) {
            float S0[4] = {0.f, 0.f, 0.f, 0.f};
            float S1[4] = {0.f, 0.f, 0.f, 0.f};
            #pragma unroll
            for (int kt = 0; kt < 4; kt++) {
                uint32_t bhf[4];
                ldsm_x4(bhf, k_b + (uint32_t)((16 * np + krow) * LDH + 16 * kt + kcol0) * 2);
                mma16816(S0, qf[kt], bhf[0], bhf[1]);
                mma16816(S1, qf[kt], bhf[2], bhf[3]);
            }

            // boundary adds only differ for the j1 tile at np==4
            const float b0e = (np < 4) ? aR0 : aB0e, b0o = (np < 4) ? aR0 : aB0o;
            const float b1e = (np < 4) ? aR1 : aB1e, b1o = (np < 4) ? aR1 : aB1o;
            uint32_t pA[4];
            pA[0] = cvtex2(fmaf(S0[0], c2, aR0), fmaf(S0[1], c2, aR0));
            pA[1] = cvtex2(fmaf(S0[2], c2, aR1), fmaf(S0[3], c2, aR1));
            pA[2] = cvtex2(fmaf(S1[0], c2, b0e), fmaf(S1[1], c2, b0o));
            pA[3] = cvtex2(fmaf(S1[2], c2, b1e), fmaf(S1[3], c2, b1o));

            #pragma unroll
            for (int dp = 0; dp < 4; dp++) {
                uint32_t vf[4];
                ldsm_x4_t(vf, v_b + (uint32_t)((16 * np + krow) * LDH + 16 * dp + kcol0) * 2);
                mma16816(O[2 * dp],     pA, vf[0], vf[2]);
                mma16816(O[2 * dp + 1], pA, vf[1], vf[3]);
            }
            // L column: V cols 64..71 (col 64 = ones)
            uint32_t vl[2];
            ldsm_x2_t(vl, v_b + (uint32_t)((16 * np + (lane & 15)) * LDH + 64) * 2);
            mma16816(LO, pA, vl[0], vl[1]);
        }

        // restage buffer with next chunk (all 4 warps done reading)
        if (c < 3) {
            __syncthreads();
            for (int i = tid; i < CL * 8; i += TPB) {
                int kk = i >> 3, d8 = (i & 7) * 8;
                size_t off = kvbase + (size_t)((c + 1) * CL + kk) * INNER + d8;
                uint32_t so = (uint32_t)(kk * LDH + d8) * 2;
                cpa16(k_b + so, g_kh + off);
                cpa16(v_b + so, g_vh + off);
            }
            asm volatile("cp.async.commit_group;");
        }
    }

    // ---- L lives in col 64 (tig==0 lanes); broadcast within each 4-lane group ----
    float Lg0 = __shfl_sync(0xffffffffu, LO[0], lane & ~3);
    float Lg1 = __shfl_sync(0xffffffffu, LO[2], lane & ~3);
    const float i0 = 1.f / Lg0, i1 = 1.f / Lg1;
    float* o0 = out + ((size_t)b * QLEN + (size_t)qt * QT + 16 * w + gid) * INNER + h * DH + 2 * tig;
    float* o1 = o0 + (size_t)8 * INNER;
    #pragma unroll
    for (int n = 0; n < 8; n++) {
        *reinterpret_cast<float2*>(o0 + 8 * n) = make_float2(O[n][0] * i0, O[n][1] * i0);
        *reinterpret_cast<float2*>(o1 + 8 * n) = make_float2(O[n][2] * i1, O[n][3] * i1);
    }
}

extern "C" void kernel_launch(void* const* d_in, const int* in_sizes, int n_in,
                              void* d_out, int out_size) {
    const float* q  = (const float*)d_in[0];
    const float* k  = (const float*)d_in[1];
    const float* v  = (const float*)d_in[2];
    const float* dd = (const float*)d_in[3];
    float* out = (float*)d_out;

    prep_kernel<<<325, 256>>>(k, v, dd);

    cudaFuncSetAttribute(ddca_kernel,
                         cudaFuncAttributeMaxDynamicSharedMemorySize, SMEM_BYTES);
    ddca_kernel<<<2 * Hh * NQT, TPB, SMEM_BYTES>>>(q, out);   // 1024 CTAs
}

// round 15
// speedup vs baseline: 1.2182x; 1.0077x over previous
#include <cuda_runtime.h>
#include <cuda_fp16.h>
#include <cstdint>

constexpr int Hh = 8, DH = 64, INNER = 512, QLEN = 4096, KLEN = 308, CL = 77, CP = 80;
constexpr int QT = 64, NQT = QLEN / QT;     // 64 query tiles of 64 rows
constexpr int TPB = 128;                    // 4 warps
constexpr int LDH = 72;                     // halves per smem row (144B, ldmatrix conflict-free)

// device scratch
__device__ __half g_kh[2 * KLEN * INNER];
__device__ __half g_vh[2 * KLEN * INNER];
__device__ float  g_cs[4];                  // (128/sum)*log2(e)
__device__ unsigned char g_act[QLEN];

// smem: Q (fp16, 64 rows) + single K buffer + single V buffer
constexpr int KV_BYTES = CP * LDH * 2;            // 11520
constexpr int OFF_QH = 0;
constexpr int OFF_K  = OFF_QH + QT * LDH * 2;     // 9216
constexpr int OFF_V  = OFF_K + KV_BYTES;          // 20736
constexpr int SMEM_BYTES = OFF_V + KV_BYTES;      // 32256 -> 7 CTAs/SM (225.8KB)

__device__ __forceinline__ uint32_t h2u(float a, float b) {
    __half2 h = __floats2half2_rn(a, b);
    return *reinterpret_cast<uint32_t*>(&h);
}
// pack {lo=exp2(zlo), hi=exp2(zhi)} computed in fp16x2
__device__ __forceinline__ uint32_t cvtex2(float zlo, float zhi) {
    uint32_t t, d;
    asm("cvt.rn.satfinite.f16x2.f32 %0, %1, %2;" : "=r"(t) : "f"(zhi), "f"(zlo));
    asm("ex2.approx.f16x2 %0, %1;" : "=r"(d) : "r"(t));
    return d;
}
__device__ __forceinline__ void ldsm_x4(uint32_t* r, uint32_t addr) {
    asm volatile("ldmatrix.sync.aligned.m8n8.x4.shared.b16 {%0,%1,%2,%3}, [%4];"
                 : "=r"(r[0]), "=r"(r[1]), "=r"(r[2]), "=r"(r[3]) : "r"(addr));
}
__device__ __forceinline__ void ldsm_x4_t(uint32_t* r, uint32_t addr) {
    asm volatile("ldmatrix.sync.aligned.m8n8.x4.trans.shared.b16 {%0,%1,%2,%3}, [%4];"
                 : "=r"(r[0]), "=r"(r[1]), "=r"(r[2]), "=r"(r[3]) : "r"(addr));
}
__device__ __forceinline__ void ldsm_x2_t(uint32_t* r, uint32_t addr) {
    asm volatile("ldmatrix.sync.aligned.m8n8.x2.trans.shared.b16 {%0,%1}, [%2];"
                 : "=r"(r[0]), "=r"(r[1]) : "r"(addr));
}
__device__ __forceinline__ void mma16816(float* c, const uint32_t* a, uint32_t b0, uint32_t b1) {
    asm volatile("mma.sync.aligned.m16n8k16.row.col.f32.f16.f16.f32 "
                 "{%0,%1,%2,%3},{%4,%5,%6,%7},{%8,%9},{%0,%1,%2,%3};"
                 : "+f"(c[0]), "+f"(c[1]), "+f"(c[2]), "+f"(c[3])
                 : "r"(a[0]), "r"(a[1]), "r"(a[2]), "r"(a[3]), "r"(b0), "r"(b1));
}
__device__ __forceinline__ void cpa16(uint32_t s, const void* g) {
    asm volatile("cp.async.cg.shared.global [%0], [%1], 16;" :: "r"(s), "l"(g));
}

// ---------------------------------------------------------------------------
// prep: K,V -> fp16; region scales (x log2e); per-query activity bytes
// ---------------------------------------------------------------------------
__global__ void __launch_bounds__(256) prep_kernel(const float* __restrict__ k,
                                                   const float* __restrict__ v,
                                                   const float* __restrict__ dd)
{
    int blk = blockIdx.x, tid = threadIdx.x;
    if (blk < 308) {
        int idx = (blk * 256 + tid) * 4;               // over 2*308*512 floats
        float4 kf = *reinterpret_cast<const float4*>(k + idx);
        float4 vf = *reinterpret_cast<const float4*>(v + idx);
        *reinterpret_cast<uint2*>(reinterpret_cast<char*>(g_kh) + (size_t)idx * 2) =
            make_uint2(h2u(kf.x, kf.y), h2u(kf.z, kf.w));
        *reinterpret_cast<uint2*>(reinterpret_cast<char*>(g_vh) + (size_t)idx * 2) =
            make_uint2(h2u(vf.x, vf.y), h2u(vf.z, vf.w));
    } else if (blk == 308) {
        __shared__ float ws[4][8];
        int w = tid >> 5, l = tid & 31;
        #pragma unroll
        for (int r = 0; r < 4; r++) {
            float s = 0.f;
            #pragma unroll
            for (int i = 0; i < 4; i++) s += dd[r * 1024 + i * 256 + tid];
            #pragma unroll
            for (int o = 16; o > 0; o >>= 1) s += __shfl_xor_sync(0xffffffffu, s, o, 32);
            if (l == 0) ws[r][w] = s;
        }
        __syncthreads();
        if (tid < 4) {
            float s = 0.f;
            #pragma unroll
            for (int ww = 0; ww < 8; ww++) s += ws[tid][ww];
            g_cs[tid] = (128.f / s) * 1.4426950408889634f;
        }
    } else {
        int qg = (blk - 309) * 256 + tid;              // 16 blocks -> 4096
        int y = qg >> 6, x = qg & 63;
        unsigned a = 0;
        #pragma unroll
        for (int r = 0; r < 4; r++)
            if (dd[r * 1024 + (y >> 1) * 32 + (x >> 1)] > 0.5f) a |= 1u << r;
        g_act[qg] = (unsigned char)a;
    }
}

// ---------------------------------------------------------------------------
// main: fp16 mma.sync attention; fp16x2 exp; L as V col 64; 7 CTAs/SM
// ---------------------------------------------------------------------------
__global__ void __launch_bounds__(TPB, 7)
ddca_kernel(const float* __restrict__ q, float* __restrict__ out)
{
    extern __shared__ char smc[];
    half* Qh = (half*)(smc + OFF_QH);
    uint32_t sbase = (uint32_t)__cvta_generic_to_shared(smc);
    const uint32_t qh_b = sbase + OFF_QH;
    const uint32_t k_b  = sbase + OFF_K;
    const uint32_t v_b  = sbase + OFF_V;

    const int tid = threadIdx.x, w = tid >> 5, lane = tid & 31;
    const int gid = lane >> 2, tig = lane & 3;
    const int bid = blockIdx.x;
    const int qt = bid & 63, bh = bid >> 6, h = bh & 7, b = bh >> 3;

    const float* qp = q + ((size_t)b * QLEN + (size_t)qt * QT) * INNER + h * DH;
    const size_t kvbase = (size_t)b * KLEN * INNER + h * DH;

    // zero V pad rows 77..79 cols 0..71, and K pad rows 77..79 (NaN safety)
    if (tid < 108) {
        reinterpret_cast<uint32_t*>(smc + OFF_V + 77 * LDH * 2)[tid] = 0;
        reinterpret_cast<uint32_t*>(smc + OFF_K + 77 * LDH * 2)[tid] = 0;
    }
    // ones column: rows 0..79, col 64 = 1.0h, cols 65..71 = 0 (never restaged)
    if (tid < 80) {
        *reinterpret_cast<uint4*>(reinterpret_cast<half*>(smc + OFF_V) + tid * LDH + 64) =
            make_uint4(0x00003C00u, 0u, 0u, 0u);
    }

    // prologue: stage chunk 0 K/V (rows 0..76, cols 0..63)
    for (int i = tid; i < CL * 8; i += TPB) {
        int kk = i >> 3, d8 = (i & 7) * 8;
        size_t off = kvbase + (size_t)kk * INNER + d8;
        uint32_t so = (uint32_t)(kk * LDH + d8) * 2;
        cpa16(k_b + so, g_kh + off);
        cpa16(v_b + so, g_vh + off);
    }
    asm volatile("cp.async.commit_group;");

    // stage Q (fp16 rounded)
    #pragma unroll
    for (int it = 0; it < 8; it++) {
        int i4 = tid + it * TPB;
        int row = i4 >> 4, dq = (i4 & 15) * 4;
        float4 t = *reinterpret_cast<const float4*>(qp + (size_t)row * INNER + dq);
        *reinterpret_cast<uint2*>(Qh + row * LDH + dq) =
            make_uint2(h2u(t.x, t.y), h2u(t.z, t.w));
    }

    const unsigned a0 = g_act[qt * QT + 16 * w + gid];
    const unsigned a1 = g_act[qt * QT + 16 * w + gid + 8];

    const int qrow  = 16 * w + (lane & 15);
    const int qcol0 = (lane >> 4) << 3;
    const int krow  = (lane & 7) + ((lane >> 4) << 3);
    const int kcol0 = ((lane >> 3) & 1) << 3;

    float O[8][4];
    #pragma unroll
    for (int n = 0; n < 8; n++)
        #pragma unroll
        for (int e = 0; e < 4; e++) O[n][e] = 0.f;
    float LO[4] = {0.f, 0.f, 0.f, 0.f};          // L accumulator fragment (col 64)
    uint32_t qf[4][4];
    bool qload = false;

    const bool bk0 = (tig <= 2), bk1 = (tig < 2);   // chunk col 72+2tig(+1) < 77

    #pragma unroll 1
    for (int c = 0; c < 4; c++) {
        asm volatile("cp.async.wait_group 0;");
        __syncthreads();                      // K/V chunk c (and Q on c=0) visible

        if (!qload) {
            #pragma unroll
            for (int kt = 0; kt < 4; kt++)
                ldsm_x4(qf[kt], qh_b + (uint32_t)(qrow * LDH + 16 * kt + qcol0) * 2);
            qload = true;
        }

        const float c2 = g_cs[c];             // L1-resident; saves register array
        const float aR0 = ((a0 >> c) & 1) ? -8.f : -1e30f;
        const float aR1 = ((a1 >> c) & 1) ? -8.f : -1e30f;

        // ---- streamed per-16-key tile: S-tile -> exp(f16x2) -> O += P V ----
        #pragma unroll
        for (int np = 0; np < 5; np++) {
            float S0[4] = {0.f, 0.f, 0.f, 0.f};
            float S1[4] = {0.f, 0.f, 0.f, 0.f};
            #pragma unroll
            for (int kt = 0; kt < 4; kt++) {
                uint32_t bhf[4];
                ldsm_x4(bhf, k_b + (uint32_t)((16 * np + krow) * LDH + 16 * kt + kcol0) * 2);
                mma16816(S0, qf[kt], bhf[0], bhf[1]);
                mma16816(S1, qf[kt], bhf[2], bhf[3]);
            }

            // boundary adds only differ for the j1 tile at np==4
            const float b0e = (np < 4 || bk0) ? aR0 : -1e30f;
            const float b0o = (np < 4 || bk1) ? aR0 : -1e30f;
            const float b1e = (np < 4 || bk0) ? aR1 : -1e30f;
            const float b1o = (np < 4 || bk1) ? aR1 : -1e30f;
            uint32_t pA[4];
            pA[0] = cvtex2(fmaf(S0[0], c2, aR0), fmaf(S0[1], c2, aR0));
            pA[1] = cvtex2(fmaf(S0[2], c2, aR1), fmaf(S0[3], c2, aR1));
            pA[2] = cvtex2(fmaf(S1[0], c2, b0e), fmaf(S1[1], c2, b0o));
            pA[3] = cvtex2(fmaf(S1[2], c2, b1e), fmaf(S1[3], c2, b1o));

            #pragma unroll
            for (int dp = 0; dp < 4; dp++) {
                uint32_t vf[4];
                ldsm_x4_t(vf, v_b + (uint32_t)((16 * np + krow) * LDH + 16 * dp + kcol0) * 2);
                mma16816(O[2 * dp],     pA, vf[0], vf[2]);
                mma16816(O[2 * dp + 1], pA, vf[1], vf[3]);
            }
            // L column: V cols 64..71 (col 64 = ones)
            uint32_t vl[2];
            ldsm_x2_t(vl, v_b + (uint32_t)((16 * np + (lane & 15)) * LDH + 64) * 2);
            mma16816(LO, pA, vl[0], vl[1]);
        }

        // restage buffer with next chunk (all 4 warps done reading)
        if (c < 3) {
            __syncthreads();
            for (int i = tid; i < CL * 8; i += TPB) {
                int kk = i >> 3, d8 = (i & 7) * 8;
                size_t off = kvbase + (size_t)((c + 1) * CL + kk) * INNER + d8;
                uint32_t so = (uint32_t)(kk * LDH + d8) * 2;
                cpa16(k_b + so, g_kh + off);
                cpa16(v_b + so, g_vh + off);
            }
            asm volatile("cp.async.commit_group;");
        }
    }

    // ---- L lives in col 64 (tig==0 lanes); broadcast within each 4-lane group ----
    float Lg0 = __shfl_sync(0xffffffffu, LO[0], lane & ~3);
    float Lg1 = __shfl_sync(0xffffffffu, LO[2], lane & ~3);
    const float i0 = 1.f / Lg0, i1 = 1.f / Lg1;
    float* o0 = out + ((size_t)b * QLEN + (size_t)qt * QT + 16 * w + gid) * INNER + h * DH + 2 * tig;
    float* o1 = o0 + (size_t)8 * INNER;
    #pragma unroll
    for (int n = 0; n < 8; n++) {
        *reinterpret_cast<float2*>(o0 + 8 * n) = make_float2(O[n][0] * i0, O[n][1] * i0);
        *reinterpret_cast<float2*>(o1 + 8 * n) = make_float2(O[n][2] * i1, O[n][3] * i1);
    }
}

extern "C" void kernel_launch(void* const* d_in, const int* in_sizes, int n_in,
                              void* d_out, int out_size) {
    const float* q  = (const float*)d_in[0];
    const float* k  = (const float*)d_in[1];
    const float* v  = (const float*)d_in[2];
    const float* dd = (const float*)d_in[3];
    float* out = (float*)d_out;

    prep_kernel<<<325, 256>>>(k, v, dd);

    cudaFuncSetAttribute(ddca_kernel,
                         cudaFuncAttributeMaxDynamicSharedMemorySize, SMEM_BYTES);
    ddca_kernel<<<2 * Hh * NQT, TPB, SMEM_BYTES>>>(q, out);   // 1024 CTAs
}